// round 12
// baseline (speedup 1.0000x reference)
#include <cuda_runtime.h>
#include <cuda_bf16.h>
#include <cstdint>

#define SEQLEN 512
#define BATCH  64
#define INP    1024
#define HID    1024
#define G4     4096
#define NCTA   128

typedef unsigned long long ull;

// ---- device scratch (static) ----
__device__ float g_G[(size_t)SEQLEN * BATCH * G4];
__device__ __nv_bfloat16 g_Whi[(size_t)G4 * HID];   // permuted: [cta][gate*8+u][k]
__device__ __nv_bfloat16 g_Wlo[(size_t)G4 * HID];
__device__ __nv_bfloat16 g_hhi[2][BATCH * HID];     // ping-pong
__device__ __nv_bfloat16 g_hlo[2][BATCH * HID];
__device__ unsigned int g_cnt[16 * 32];             // per-producer-group counters (128B apart)

// ---- f32x2 helpers (fp32 input GEMM) ----
static __device__ __forceinline__ void ffma2(ull& a, ull x, ull y) {
    asm("fma.rn.f32x2 %0, %1, %2, %0;" : "+l"(a) : "l"(x), "l"(y));
}
static __device__ __forceinline__ ull pack2(float x, float y) {
    ull r; asm("mov.b64 %0, {%1, %2};" : "=l"(r) : "f"(x), "f"(y)); return r;
}
static __device__ __forceinline__ float2 unpack2(ull v) {
    float lo, hi; asm("mov.b64 {%0, %1}, %2;" : "=f"(lo), "=f"(hi) : "l"(v));
    return make_float2(lo, hi);
}

// ---- warp MMA primitives ----
static __device__ __forceinline__ uint32_t smem_u32(const void* p) {
    uint32_t a;
    asm("{ .reg .u64 t; cvta.to.shared.u64 t, %1; cvt.u32.u64 %0, t; }" : "=r"(a) : "l"(p));
    return a;
}
static __device__ __forceinline__ void ldsm4(uint32_t& r0, uint32_t& r1,
                                             uint32_t& r2, uint32_t& r3, uint32_t a) {
    asm volatile("ldmatrix.sync.aligned.m8n8.x4.shared.b16 {%0,%1,%2,%3}, [%4];"
                 : "=r"(r0), "=r"(r1), "=r"(r2), "=r"(r3) : "r"(a));
}
static __device__ __forceinline__ void mma16816(float* d, const uint32_t* a,
                                                uint32_t b0, uint32_t b1) {
    asm volatile("mma.sync.aligned.m16n8k16.row.col.f32.bf16.bf16.f32 "
                 "{%0,%1,%2,%3}, {%4,%5,%6,%7}, {%8,%9}, {%0,%1,%2,%3};"
                 : "+f"(d[0]), "+f"(d[1]), "+f"(d[2]), "+f"(d[3])
                 : "r"(a[0]), "r"(a[1]), "r"(a[2]), "r"(a[3]), "r"(b0), "r"(b1));
}
static __device__ __forceinline__ void cpa16(uint32_t dst, const void* src) {
    asm volatile("cp.async.cg.shared.global [%0], [%1], 16;" :: "r"(dst), "l"(src));
}
#define CP_COMMIT() asm volatile("cp.async.commit_group;" ::: "memory")
#define CP_WAIT1()  asm volatile("cp.async.wait_group 1;" ::: "memory")
#define CP_WAIT0()  asm volatile("cp.async.wait_group 0;" ::: "memory")

static __device__ __forceinline__ float sigf(float x) {
    return 1.0f / (1.0f + __expf(-x));
}
static __device__ __forceinline__ float tanhfast(float x) {
    return 2.0f / (1.0f + __expf(-2.0f * x)) - 1.0f;
}
// spin until producer-group g's counter reaches target (warp-converged)
static __device__ __forceinline__ void wait_cnt(int g, unsigned int target) {
    unsigned int v;
    do {
        asm volatile("ld.acquire.gpu.global.u32 %0, [%1];"
                     : "=r"(v) : "l"(&g_cnt[g * 32]) : "memory");
    } while (v < target);
}

// ---- init ----
__global__ void zero_state_kernel() {
    int i = blockIdx.x * blockDim.x + threadIdx.x;
    if (i < BATCH * HID) {
        g_hhi[0][i] = __float2bfloat16(0.0f);
        g_hlo[0][i] = __float2bfloat16(0.0f);
        g_hhi[1][i] = __float2bfloat16(0.0f);
        g_hlo[1][i] = __float2bfloat16(0.0f);
    }
    if (i < 16 * 32) g_cnt[i] = 0u;
}

// ---- split + permute W_hh: cta = j>>3, local row = gate*8 + (j&7) ----
__global__ void wsplit_kernel(const float* __restrict__ Whh) {
    int idx = blockIdx.x * blockDim.x + threadIdx.x;
    if (idx >= G4 * HID) return;
    int gr = idx >> 10;
    int k  = idx & 1023;
    int gate = gr >> 10;
    int j    = gr & 1023;
    int cta  = j >> 3;
    int u    = j & 7;
    size_t dst = ((size_t)cta * 32 + gate * 8 + u) * 1024 + k;
    float w = Whh[(size_t)gr * 1024 + k];
    __nv_bfloat16 hi = __float2bfloat16(w);
    float res = w - __bfloat162float(hi);
    g_Whi[dst] = hi;
    g_Wlo[dst] = __float2bfloat16(res);
}

// ---- big input GEMM (proven): G = X @ W_ih^T + (b_ih + b_hh) ----
__global__ __launch_bounds__(256) void gemm_gates(
    const float* __restrict__ X, const float* __restrict__ Wih,
    const float* __restrict__ bih, const float* __restrict__ bhh)
{
    __shared__ __align__(16) float As[8][132];
    __shared__ __align__(16) float Bs[8][132];
    const int tid = threadIdx.x;
    const int bn = blockIdx.x, bm = blockIdx.y;
    const int lr = tid >> 1, lk = (tid & 1) << 2;
    const float* Ag = X   + (size_t)(bm * 128 + lr) * INP + lk;
    const float* Bg = Wih + (size_t)(bn * 128 + lr) * INP + lk;
    const int tx = tid & 15, ty = tid >> 4;

    ull acc[8][4];
    #pragma unroll
    for (int i = 0; i < 8; i++)
        #pragma unroll
        for (int j = 0; j < 4; j++) acc[i][j] = 0ull;

    for (int k0 = 0; k0 < INP; k0 += 8) {
        float4 av = *(const float4*)(Ag + k0);
        float4 bv = *(const float4*)(Bg + k0);
        __syncthreads();
        As[lk+0][lr] = av.x; As[lk+1][lr] = av.y; As[lk+2][lr] = av.z; As[lk+3][lr] = av.w;
        Bs[lk+0][lr] = bv.x; Bs[lk+1][lr] = bv.y; Bs[lk+2][lr] = bv.z; Bs[lk+3][lr] = bv.w;
        __syncthreads();
        #pragma unroll
        for (int kk = 0; kk < 8; kk++) {
            float4 a0 = *(const float4*)&As[kk][ty * 8];
            float4 a1 = *(const float4*)&As[kk][ty * 8 + 4];
            ulonglong2 b0 = *(const ulonglong2*)&Bs[kk][tx * 8];
            ulonglong2 b1 = *(const ulonglong2*)&Bs[kk][tx * 8 + 4];
            float a[8] = {a0.x,a0.y,a0.z,a0.w,a1.x,a1.y,a1.z,a1.w};
            #pragma unroll
            for (int i = 0; i < 8; i++) {
                ull aa = pack2(a[i], a[i]);
                ffma2(acc[i][0], aa, b0.x); ffma2(acc[i][1], aa, b0.y);
                ffma2(acc[i][2], aa, b1.x); ffma2(acc[i][3], aa, b1.y);
            }
        }
    }
    const int col0 = bn * 128 + tx * 8;
    float bias[8];
    #pragma unroll
    for (int j = 0; j < 8; j++) bias[j] = bih[col0 + j] + bhh[col0 + j];
    #pragma unroll
    for (int i = 0; i < 8; i++) {
        int row = bm * 128 + ty * 8 + i;
        float2 p0 = unpack2(acc[i][0]), p1 = unpack2(acc[i][1]);
        float2 p2 = unpack2(acc[i][2]), p3 = unpack2(acc[i][3]);
        float4 o0 = make_float4(p0.x+bias[0], p0.y+bias[1], p1.x+bias[2], p1.y+bias[3]);
        float4 o1 = make_float4(p2.x+bias[4], p2.y+bias[5], p3.x+bias[6], p3.y+bias[7]);
        *(float4*)&g_G[(size_t)row * G4 + col0    ] = o0;
        *(float4*)&g_G[(size_t)row * G4 + col0 + 4] = o1;
    }
}

// ---- smem layout (bytes) ----
#define WSTRIDE   1032                      // halves per W row (pad -> conflict-free)
#define SM_W      0                         // Whi [32][1032], then Wlo
#define WHALF_SZ  (32 * WSTRIDE * 2)        // 66048
#define SM_H      (2 * WHALF_SZ)            // 132096
#define HSTRIDE   72                        // halves per h row (pad 8)
#define HB_SZ     (64 * HSTRIDE * 2)        // 9216 per (hi/lo)
#define HBUF_SZ   (2 * HB_SZ)               // 18432 (hi+lo per buffer)
#define SM_GATES  (SM_H + 2 * HBUF_SZ)      // float[32][68]
#define SM_TOTAL  (SM_GATES + 32 * 68 * 4)  // 177664

static __device__ __forceinline__ void issue_chunk(
    int c, uint32_t hbuf, const char* hhi, const char* hlo, int tid)
{
    #pragma unroll
    for (int r = 0; r < 2; r++) {
        int i = tid + r * 256;              // 0..511
        int row = i >> 3, seg = i & 7;
        uint32_t d = hbuf + row * (HSTRIDE * 2) + seg * 16;
        cpa16(d,         hhi + (size_t)row * 2048 + c * 128 + seg * 16);
        cpa16(d + HB_SZ, hlo + (size_t)row * 2048 + c * 128 + seg * 16);
    }
}

// ---- persistent recurrence on HMMA tensor cores, producer-group wavefront sync ----
// 128 CTAs x 256 thr (8 warps = 2M x 4N). CTA: 32 D-rows (4 gates x 8 units), N=64, K=1024.
// Chunk c of step t only needs producer group c (CTAs 8c..8c+8) done with step t-1.
__global__ __launch_bounds__(256) void lstm_persist(
    const float* __restrict__ keep,
    const int*   __restrict__ training,
    float*       __restrict__ final_out)
{
    extern __shared__ __align__(16) char sm[];
    const uint32_t smb = smem_u32(sm);
    const int tid  = threadIdx.x;
    const int wid  = tid >> 5;
    const int lane = tid & 31;
    const int cta  = blockIdx.x;

    // load W slice into smem once
    {
        const char* whi = (const char*)(g_Whi + (size_t)cta * 32 * 1024);
        const char* wlo = (const char*)(g_Wlo + (size_t)cta * 32 * 1024);
        for (int i = tid; i < 4096; i += 256) {
            int row = i >> 7, seg = i & 127;
            uint32_t off = row * (WSTRIDE * 2) + seg * 16;
            *(uint4*)(sm + SM_W + off)            = *(const uint4*)(whi + row * 2048 + seg * 16);
            *(uint4*)(sm + SM_W + WHALF_SZ + off) = *(const uint4*)(wlo + row * 2048 + seg * 16);
        }
    }
    __syncthreads();

    const int   trn   = *training;
    const float scale = trn ? (1.0f / 0.9f) : 1.0f;

    // MMA tiling
    const int wm = wid >> 2;
    const int wn = wid & 3;
    const int lr = lane & 7;
    const int g  = lane >> 3;
    const uint32_t aoff = smb + SM_W +
        (uint32_t)((wm * 16 + lr + ((g & 1) << 3)) * WSTRIDE + ((g >> 1) << 3)) * 2;
    const uint32_t boff =
        (uint32_t)((wn * 16 + lr + ((g >> 1) << 3)) * HSTRIDE + ((g & 1) << 3)) * 2;

    float* gates = (float*)(sm + SM_GATES);

    // cell mapping
    const int u  = tid >> 5;
    const int b2 = tid & 31;
    const int j  = cta * 8 + u;
    const int mygrp = cta >> 3;

    float creg[2] = {0.0f, 0.0f};

    #pragma unroll 1
    for (int t = 0; t < SEQLEN; t++) {
        const int rb = t & 1;
        const char* hhi = (const char*)g_hhi[rb];
        const char* hlo = (const char*)g_hlo[rb];
        const unsigned int tgt = 8u * (unsigned int)t;   // h(t-1) ready threshold

        // prefetch G + keep (independent of h; overlaps counter waits)
        float garr[8], karr[2];
        #pragma unroll
        for (int gg = 0; gg < 4; gg++)
            #pragma unroll
            for (int i = 0; i < 2; i++)
                garr[gg * 2 + i] =
                    __ldcg(&g_G[((size_t)t * BATCH + 2 * b2 + i) * G4 + gg * 1024 + j]);
        if (trn) {
            #pragma unroll
            for (int i = 0; i < 2; i++)
                karr[i] = __ldcg(&keep[((size_t)t * BATCH + 2 * b2 + i) * HID + j]);
        }

        if (t) wait_cnt(0, tgt);
        issue_chunk(0, smb + SM_H, hhi, hlo, tid); CP_COMMIT();
        if (t) wait_cnt(1, tgt);
        issue_chunk(1, smb + SM_H + HBUF_SZ, hhi, hlo, tid); CP_COMMIT();

        float acc0[4] = {0, 0, 0, 0}, acc1[4] = {0, 0, 0, 0};

        #pragma unroll 1
        for (int c = 0; c < 16; c++) {
            if (c < 15) { CP_WAIT1(); } else { CP_WAIT0(); }
            __syncthreads();

            const uint32_t hb = smb + SM_H + (c & 1) * HBUF_SZ;
            const uint32_t ac = aoff + c * 128;
            #pragma unroll
            for (int ks = 0; ks < 4; ks++) {
                const uint32_t kb = ks * 32;
                uint32_t ah[4], al[4], bh[4], bl[4];
                ldsm4(ah[0], ah[1], ah[2], ah[3], ac + kb);
                ldsm4(al[0], al[1], al[2], al[3], ac + WHALF_SZ + kb);
                ldsm4(bh[0], bh[1], bh[2], bh[3], hb + boff + kb);
                ldsm4(bl[0], bl[1], bl[2], bl[3], hb + boff + HB_SZ + kb);
                mma16816(acc0, ah, bh[0], bh[1]);
                mma16816(acc0, ah, bl[0], bl[1]);
                mma16816(acc0, al, bh[0], bh[1]);
                mma16816(acc1, ah, bh[2], bh[3]);
                mma16816(acc1, ah, bl[2], bl[3]);
                mma16816(acc1, al, bh[2], bh[3]);
            }
            __syncthreads();
            if (c + 2 < 16) {
                if (t) wait_cnt(c + 2, tgt);
                issue_chunk(c + 2, hb, hhi, hlo, tid);
                CP_COMMIT();
            }
        }

        // D -> gates smem
        {
            const int r = lane >> 2, cb = (lane & 3) * 2;
            float* g0 = &gates[(wm * 16 + r) * 68 + wn * 16 + cb];
            float* g1 = &gates[(wm * 16 + r + 8) * 68 + wn * 16 + cb];
            g0[0] = acc0[0]; g0[1] = acc0[1];
            g1[0] = acc0[2]; g1[1] = acc0[3];
            g0[8] = acc1[0]; g0[9] = acc1[1];
            g1[8] = acc1[2]; g1[9] = acc1[3];
        }
        __syncthreads();

        // cell update; write h(t) into buffer rb^1
        __nv_bfloat16* whhi = g_hhi[rb ^ 1];
        __nv_bfloat16* whlo = g_hlo[rb ^ 1];
        #pragma unroll
        for (int i = 0; i < 2; i++) {
            const int b = 2 * b2 + i;
            float iv = gates[(0 * 8 + u) * 68 + b] + garr[0 * 2 + i];
            float fv = gates[(1 * 8 + u) * 68 + b] + garr[1 * 2 + i];
            float gv = gates[(2 * 8 + u) * 68 + b] + garr[2 * 2 + i];
            float ov = gates[(3 * 8 + u) * 68 + b] + garr[3 * 2 + i];
            float ig = sigf(iv);
            float fg = sigf(fv);
            float gg = tanhfast(gv);
            float og = sigf(ov);
            float cc = fg * creg[i] + ig * gg;
            creg[i] = cc;
            float h = og * tanhfast(cc);
            if (trn) h *= karr[i] * scale;
            __nv_bfloat16 hh = __float2bfloat16(h);
            float res = h - __bfloat162float(hh);
            __stcg(&whhi[b * HID + j], hh);
            __stcg(&whlo[b * HID + j], __float2bfloat16(res));
            if (t == SEQLEN - 1) final_out[b * HID + j] = h;
        }

        // publish: h(t) visible, then bump this CTA's producer-group counter
        __threadfence();
        __syncthreads();
        if (tid == 0) atomicAdd(&g_cnt[mygrp * 32], 1u);
    }
}

extern "C" void kernel_launch(void* const* d_in, const int* in_sizes, int n_in,
                              void* d_out, int out_size) {
    const float* x    = (const float*)d_in[0];
    const float* keep = (const float*)d_in[1];
    const float* Wih  = (const float*)d_in[2];
    const float* Whh  = (const float*)d_in[3];
    const float* bih  = (const float*)d_in[4];
    const float* bhh  = (const float*)d_in[5];
    const int*   trn  = (const int*)d_in[6];
    float* out = (float*)d_out;

    cudaFuncSetAttribute(lstm_persist, cudaFuncAttributeMaxDynamicSharedMemorySize, SM_TOTAL);

    zero_state_kernel<<<256, 256>>>();
    wsplit_kernel<<<(G4 * HID + 255) / 256, 256>>>(Whh);
    dim3 g1(32, 256);
    gemm_gates<<<g1, 256>>>(x, Wih, bih, bhh);
    lstm_persist<<<NCTA, 256, SM_TOTAL>>>(keep, trn, out);
}

// round 13
// speedup vs baseline: 1.1467x; 1.1467x over previous
#include <cuda_runtime.h>
#include <cuda_bf16.h>
#include <cstdint>

#define SEQLEN 512
#define BATCH  64
#define INP    1024
#define HID    1024
#define G4     4096
#define NCTA   128

typedef unsigned long long ull;

// ---- device scratch (static) ----
__device__ float g_G[(size_t)SEQLEN * BATCH * G4];
__device__ __nv_bfloat16 g_Whi[(size_t)G4 * HID];   // permuted: [cta][gate*8+u][k]
__device__ __nv_bfloat16 g_Wlo[(size_t)G4 * HID];
__device__ __nv_bfloat16 g_hhi[2][BATCH * HID];     // ping-pong
__device__ __nv_bfloat16 g_hlo[2][BATCH * HID];
__device__ unsigned int g_bar;
__device__ unsigned int g_epoch;

// ---- f32x2 helpers (fp32 input GEMM) ----
static __device__ __forceinline__ void ffma2(ull& a, ull x, ull y) {
    asm("fma.rn.f32x2 %0, %1, %2, %0;" : "+l"(a) : "l"(x), "l"(y));
}
static __device__ __forceinline__ ull pack2(float x, float y) {
    ull r; asm("mov.b64 %0, {%1, %2};" : "=l"(r) : "f"(x), "f"(y)); return r;
}
static __device__ __forceinline__ float2 unpack2(ull v) {
    float lo, hi; asm("mov.b64 {%0, %1}, %2;" : "=f"(lo), "=f"(hi) : "l"(v));
    return make_float2(lo, hi);
}

// ---- warp MMA primitives ----
static __device__ __forceinline__ uint32_t smem_u32(const void* p) {
    uint32_t a;
    asm("{ .reg .u64 t; cvta.to.shared.u64 t, %1; cvt.u32.u64 %0, t; }" : "=r"(a) : "l"(p));
    return a;
}
static __device__ __forceinline__ void ldsm4(uint32_t& r0, uint32_t& r1,
                                             uint32_t& r2, uint32_t& r3, uint32_t a) {
    asm volatile("ldmatrix.sync.aligned.m8n8.x4.shared.b16 {%0,%1,%2,%3}, [%4];"
                 : "=r"(r0), "=r"(r1), "=r"(r2), "=r"(r3) : "r"(a));
}
static __device__ __forceinline__ void mma16816(float* d, const uint32_t* a,
                                                uint32_t b0, uint32_t b1) {
    asm volatile("mma.sync.aligned.m16n8k16.row.col.f32.bf16.bf16.f32 "
                 "{%0,%1,%2,%3}, {%4,%5,%6,%7}, {%8,%9}, {%0,%1,%2,%3};"
                 : "+f"(d[0]), "+f"(d[1]), "+f"(d[2]), "+f"(d[3])
                 : "r"(a[0]), "r"(a[1]), "r"(a[2]), "r"(a[3]), "r"(b0), "r"(b1));
}
static __device__ __forceinline__ void cpa16(uint32_t dst, const void* src) {
    asm volatile("cp.async.cg.shared.global [%0], [%1], 16;" :: "r"(dst), "l"(src));
}
#define CP_COMMIT() asm volatile("cp.async.commit_group;" ::: "memory")
#define CP_WAIT1()  asm volatile("cp.async.wait_group 1;" ::: "memory")
#define CP_WAIT0()  asm volatile("cp.async.wait_group 0;" ::: "memory")

static __device__ __forceinline__ float sigf(float x) {
    return 1.0f / (1.0f + __expf(-x));
}
static __device__ __forceinline__ float tanhfast(float x) {
    return 2.0f / (1.0f + __expf(-2.0f * x)) - 1.0f;
}

// ---- init ----
__global__ void zero_state_kernel() {
    int i = blockIdx.x * blockDim.x + threadIdx.x;
    if (i < BATCH * HID) {
        g_hhi[0][i] = __float2bfloat16(0.0f);
        g_hlo[0][i] = __float2bfloat16(0.0f);
        g_hhi[1][i] = __float2bfloat16(0.0f);
        g_hlo[1][i] = __float2bfloat16(0.0f);
    }
    if (i == 0) { g_bar = 0u; g_epoch = 0u; }
}

// ---- split + permute W_hh: cta = j>>3, local row = gate*8 + (j&7) ----
__global__ void wsplit_kernel(const float* __restrict__ Whh) {
    int idx = blockIdx.x * blockDim.x + threadIdx.x;
    if (idx >= G4 * HID) return;
    int gr = idx >> 10;
    int k  = idx & 1023;
    int gate = gr >> 10;
    int j    = gr & 1023;
    int cta  = j >> 3;
    int u    = j & 7;
    size_t dst = ((size_t)cta * 32 + gate * 8 + u) * 1024 + k;
    float w = Whh[(size_t)gr * 1024 + k];
    __nv_bfloat16 hi = __float2bfloat16(w);
    float res = w - __bfloat162float(hi);
    g_Whi[dst] = hi;
    g_Wlo[dst] = __float2bfloat16(res);
}

// ---- big input GEMM (proven): G = X @ W_ih^T + (b_ih + b_hh) ----
__global__ __launch_bounds__(256) void gemm_gates(
    const float* __restrict__ X, const float* __restrict__ Wih,
    const float* __restrict__ bih, const float* __restrict__ bhh)
{
    __shared__ __align__(16) float As[8][132];
    __shared__ __align__(16) float Bs[8][132];
    const int tid = threadIdx.x;
    const int bn = blockIdx.x, bm = blockIdx.y;
    const int lr = tid >> 1, lk = (tid & 1) << 2;
    const float* Ag = X   + (size_t)(bm * 128 + lr) * INP + lk;
    const float* Bg = Wih + (size_t)(bn * 128 + lr) * INP + lk;
    const int tx = tid & 15, ty = tid >> 4;

    ull acc[8][4];
    #pragma unroll
    for (int i = 0; i < 8; i++)
        #pragma unroll
        for (int j = 0; j < 4; j++) acc[i][j] = 0ull;

    for (int k0 = 0; k0 < INP; k0 += 8) {
        float4 av = *(const float4*)(Ag + k0);
        float4 bv = *(const float4*)(Bg + k0);
        __syncthreads();
        As[lk+0][lr] = av.x; As[lk+1][lr] = av.y; As[lk+2][lr] = av.z; As[lk+3][lr] = av.w;
        Bs[lk+0][lr] = bv.x; Bs[lk+1][lr] = bv.y; Bs[lk+2][lr] = bv.z; Bs[lk+3][lr] = bv.w;
        __syncthreads();
        #pragma unroll
        for (int kk = 0; kk < 8; kk++) {
            float4 a0 = *(const float4*)&As[kk][ty * 8];
            float4 a1 = *(const float4*)&As[kk][ty * 8 + 4];
            ulonglong2 b0 = *(const ulonglong2*)&Bs[kk][tx * 8];
            ulonglong2 b1 = *(const ulonglong2*)&Bs[kk][tx * 8 + 4];
            float a[8] = {a0.x,a0.y,a0.z,a0.w,a1.x,a1.y,a1.z,a1.w};
            #pragma unroll
            for (int i = 0; i < 8; i++) {
                ull aa = pack2(a[i], a[i]);
                ffma2(acc[i][0], aa, b0.x); ffma2(acc[i][1], aa, b0.y);
                ffma2(acc[i][2], aa, b1.x); ffma2(acc[i][3], aa, b1.y);
            }
        }
    }
    const int col0 = bn * 128 + tx * 8;
    float bias[8];
    #pragma unroll
    for (int j = 0; j < 8; j++) bias[j] = bih[col0 + j] + bhh[col0 + j];
    #pragma unroll
    for (int i = 0; i < 8; i++) {
        int row = bm * 128 + ty * 8 + i;
        float2 p0 = unpack2(acc[i][0]), p1 = unpack2(acc[i][1]);
        float2 p2 = unpack2(acc[i][2]), p3 = unpack2(acc[i][3]);
        float4 o0 = make_float4(p0.x+bias[0], p0.y+bias[1], p1.x+bias[2], p1.y+bias[3]);
        float4 o1 = make_float4(p2.x+bias[4], p2.y+bias[5], p3.x+bias[6], p3.y+bias[7]);
        *(float4*)&g_G[(size_t)row * G4 + col0    ] = o0;
        *(float4*)&g_G[(size_t)row * G4 + col0 + 4] = o1;
    }
}

// ---- smem layout (bytes) ----
#define WSTRIDE   1032                      // halves per W row (68 words mod 32 = 4 -> conflict-free)
#define SM_W      0                         // Whi [32][1032], then Wlo
#define WHALF_SZ  (32 * WSTRIDE * 2)        // 66048
#define SM_H      (2 * WHALF_SZ)            // 132096
#define HSTRIDE   136                       // halves per h row for 128-k chunk (pad 8)
#define HB_SZ     (64 * HSTRIDE * 2)        // 17408 per (hi/lo)
#define HBUF_SZ   (2 * HB_SZ)               // 34816 (hi+lo per buffer)
#define SM_GATES  (SM_H + 2 * HBUF_SZ)      // 201728: float[32][68]
#define SM_TOTAL  (SM_GATES + 32 * 68 * 4)  // 210432

// 128-k chunk: 64 rows x 16 x 16B per half
static __device__ __forceinline__ void issue_chunk(
    int c, uint32_t hbuf, const char* hhi, const char* hlo, int tid)
{
    #pragma unroll
    for (int r = 0; r < 4; r++) {
        int i = tid + r * 256;              // 0..1023
        int row = i >> 4, seg = i & 15;
        uint32_t d = hbuf + row * (HSTRIDE * 2) + seg * 16;
        cpa16(d,         hhi + (size_t)row * 2048 + c * 256 + seg * 16);
        cpa16(d + HB_SZ, hlo + (size_t)row * 2048 + c * 256 + seg * 16);
    }
}

// ---- persistent recurrence on HMMA tensor cores ----
// 128 CTAs x 256 thr (8 warps = 2M x 4N). CTA: 32 D-rows (4 gates x 8 units), N=64, K=1024.
// 8 chunks of 128-k, double-buffered; epoch-broadcast grid barrier.
__global__ __launch_bounds__(256) void lstm_persist(
    const float* __restrict__ keep,
    const int*   __restrict__ training,
    float*       __restrict__ final_out)
{
    extern __shared__ __align__(16) char sm[];
    const uint32_t smb = smem_u32(sm);
    const int tid  = threadIdx.x;
    const int wid  = tid >> 5;
    const int lane = tid & 31;
    const int cta  = blockIdx.x;

    // load W slice into smem once
    {
        const char* whi = (const char*)(g_Whi + (size_t)cta * 32 * 1024);
        const char* wlo = (const char*)(g_Wlo + (size_t)cta * 32 * 1024);
        for (int i = tid; i < 4096; i += 256) {
            int row = i >> 7, seg = i & 127;
            uint32_t off = row * (WSTRIDE * 2) + seg * 16;
            *(uint4*)(sm + SM_W + off)            = *(const uint4*)(whi + row * 2048 + seg * 16);
            *(uint4*)(sm + SM_W + WHALF_SZ + off) = *(const uint4*)(wlo + row * 2048 + seg * 16);
        }
    }
    __syncthreads();

    const int   trn   = *training;
    const float scale = trn ? (1.0f / 0.9f) : 1.0f;

    // MMA tiling
    const int wm = wid >> 2;
    const int wn = wid & 3;
    const int lr = lane & 7;
    const int g  = lane >> 3;
    const uint32_t aoff = smb + SM_W +
        (uint32_t)((wm * 16 + lr + ((g & 1) << 3)) * WSTRIDE + ((g >> 1) << 3)) * 2;
    const uint32_t boff =
        (uint32_t)((wn * 16 + lr + ((g >> 1) << 3)) * HSTRIDE + ((g & 1) << 3)) * 2;

    float* gates = (float*)(sm + SM_GATES);

    // cell mapping
    const int u  = tid >> 5;
    const int b2 = tid & 31;
    const int j  = cta * 8 + u;

    float creg[2] = {0.0f, 0.0f};

    #pragma unroll 1
    for (int t = 0; t < SEQLEN; t++) {
        const int rb = t & 1;
        const char* hhi = (const char*)g_hhi[rb];
        const char* hlo = (const char*)g_hlo[rb];

        // prefetch G + keep (independent of h; overlaps barrier wait)
        float garr[8], karr[2];
        #pragma unroll
        for (int gg = 0; gg < 4; gg++)
            #pragma unroll
            for (int i = 0; i < 2; i++)
                garr[gg * 2 + i] =
                    __ldcg(&g_G[((size_t)t * BATCH + 2 * b2 + i) * G4 + gg * 1024 + j]);
        if (trn) {
            #pragma unroll
            for (int i = 0; i < 2; i++)
                karr[i] = __ldcg(&keep[((size_t)t * BATCH + 2 * b2 + i) * HID + j]);
        }

        // grid barrier: spin on write-once epoch flag (no contention with arrivers)
        if (t > 0) {
            if (tid == 0) {
                unsigned int e;
                do {
                    asm volatile("ld.acquire.gpu.global.u32 %0, [%1];"
                                 : "=r"(e) : "l"(&g_epoch) : "memory");
                } while (e < (unsigned int)t);
            }
            __syncthreads();
        }

        issue_chunk(0, smb + SM_H, hhi, hlo, tid); CP_COMMIT();
        issue_chunk(1, smb + SM_H + HBUF_SZ, hhi, hlo, tid); CP_COMMIT();

        float acc0[4] = {0, 0, 0, 0}, acc1[4] = {0, 0, 0, 0};

        #pragma unroll 1
        for (int c = 0; c < 8; c++) {
            if (c < 7) { CP_WAIT1(); } else { CP_WAIT0(); }
            __syncthreads();

            const uint32_t hb = smb + SM_H + (c & 1) * HBUF_SZ;
            const uint32_t ac = aoff + c * 256;
            #pragma unroll
            for (int ks = 0; ks < 8; ks++) {
                const uint32_t kb = ks * 32;
                uint32_t ah[4], al[4], bh[4], bl[4];
                ldsm4(ah[0], ah[1], ah[2], ah[3], ac + kb);
                ldsm4(al[0], al[1], al[2], al[3], ac + WHALF_SZ + kb);
                ldsm4(bh[0], bh[1], bh[2], bh[3], hb + boff + kb);
                ldsm4(bl[0], bl[1], bl[2], bl[3], hb + boff + HB_SZ + kb);
                mma16816(acc0, ah, bh[0], bh[1]);
                mma16816(acc0, ah, bl[0], bl[1]);
                mma16816(acc0, al, bh[0], bh[1]);
                mma16816(acc1, ah, bh[2], bh[3]);
                mma16816(acc1, ah, bl[2], bl[3]);
                mma16816(acc1, al, bh[2], bh[3]);
            }
            __syncthreads();
            if (c + 2 < 8) { issue_chunk(c + 2, hb, hhi, hlo, tid); CP_COMMIT(); }
        }

        // D -> gates smem
        {
            const int r = lane >> 2, cb = (lane & 3) * 2;
            float* g0 = &gates[(wm * 16 + r) * 68 + wn * 16 + cb];
            float* g1 = &gates[(wm * 16 + r + 8) * 68 + wn * 16 + cb];
            g0[0] = acc0[0]; g0[1] = acc0[1];
            g1[0] = acc0[2]; g1[1] = acc0[3];
            g0[8] = acc1[0]; g0[9] = acc1[1];
            g1[8] = acc1[2]; g1[9] = acc1[3];
        }
        __syncthreads();

        // cell update; write h(t) into buffer rb^1
        __nv_bfloat16* whhi = g_hhi[rb ^ 1];
        __nv_bfloat16* whlo = g_hlo[rb ^ 1];
        #pragma unroll
        for (int i = 0; i < 2; i++) {
            const int b = 2 * b2 + i;
            float iv = gates[(0 * 8 + u) * 68 + b] + garr[0 * 2 + i];
            float fv = gates[(1 * 8 + u) * 68 + b] + garr[1 * 2 + i];
            float gv = gates[(2 * 8 + u) * 68 + b] + garr[2 * 2 + i];
            float ov = gates[(3 * 8 + u) * 68 + b] + garr[3 * 2 + i];
            float ig = sigf(iv);
            float fg = sigf(fv);
            float gg = tanhfast(gv);
            float og = sigf(ov);
            float cc = fg * creg[i] + ig * gg;
            creg[i] = cc;
            float h = og * tanhfast(cc);
            if (trn) h *= karr[i] * scale;
            __nv_bfloat16 hh = __float2bfloat16(h);
            float res = h - __bfloat162float(hh);
            __stcg(&whhi[b * HID + j], hh);
            __stcg(&whlo[b * HID + j], __float2bfloat16(res));
            if (t == SEQLEN - 1) final_out[b * HID + j] = h;
        }

        // arrive: h(t) visible; last arriver broadcasts the epoch
        __threadfence();
        __syncthreads();
        if (tid == 0) {
            unsigned int old = atomicAdd(&g_bar, 1u);
            if (old == (unsigned int)NCTA * (unsigned int)(t + 1) - 1u) {
                unsigned int e = (unsigned int)(t + 1);
                asm volatile("st.release.gpu.global.u32 [%0], %1;"
                             :: "l"(&g_epoch), "r"(e) : "memory");
            }
        }
    }
}

extern "C" void kernel_launch(void* const* d_in, const int* in_sizes, int n_in,
                              void* d_out, int out_size) {
    const float* x    = (const float*)d_in[0];
    const float* keep = (const float*)d_in[1];
    const float* Wih  = (const float*)d_in[2];
    const float* Whh  = (const float*)d_in[3];
    const float* bih  = (const float*)d_in[4];
    const float* bhh  = (const float*)d_in[5];
    const int*   trn  = (const int*)d_in[6];
    float* out = (float*)d_out;

    cudaFuncSetAttribute(lstm_persist, cudaFuncAttributeMaxDynamicSharedMemorySize, SM_TOTAL);

    zero_state_kernel<<<256, 256>>>();
    wsplit_kernel<<<(G4 * HID + 255) / 256, 256>>>(Whh);
    dim3 g1(32, 256);
    gemm_gates<<<g1, 256>>>(x, Wih, bih, bhh);
    lstm_persist<<<NCTA, 256, SM_TOTAL>>>(keep, trn, out);
}